// round 4
// baseline (speedup 1.0000x reference)
#include <cuda_runtime.h>
#include <cuda_bf16.h>

// Problem constants
#define NRAYS   8192
#define KG      4096
#define NGROUP  64          // ray groups (equal size)
#define GSZ     128         // rays per group
#define GRIDY   8           // gaussian splits per group (blockIdx.y)
#define EV_WARPS 4          // warps per eval block
#define NCOL    (GRIDY * EV_WARPS)   // 32 partial columns
#define QCUT    30.0f       // skip if q_min > QCUT  (2^-30*4096 ~ 4e-6 logit err)

// s = sqrt(0.5 * log2(e)) : folds exp(-0.5 q) -> 2^(-||W d||^2)
#define SCALE_S 0.8493281132464818f

// ---- scratch (__device__ globals; no allocations) -------------------------
__device__ __align__(16) float  g_coef[KG * 16];            // W(10), nc(4), lab, pad
__device__ __align__(16) float  g_abs [KG * 12];            // |W|(10), pad(2)
__device__ __align__(16) float4 g_rays[NRAYS];              // sorted rays
__device__ int    g_perm[NRAYS];                            // sorted slot -> original n
__device__ __align__(16) float4 g_gctr[NGROUP];             // group bbox center
__device__ __align__(16) float4 g_ghw [NGROUP];             // group bbox half-width
__device__ float  g_partial[NRAYS * NCOL];                  // 1 MB

__device__ __forceinline__ float ex2f(float x) {
    float e;
    asm("ex2.approx.ftz.f32 %0, %1;" : "=f"(e) : "f"(x));
    return e;
}

// ---------------------------------------------------------------------------
// Kernel A: grid 5 x 1024 threads.
//   blocks 0..3 : gaussian setup (W = s*L^{-1}, nc = -W*mu, |W|)
//   block  4    : deterministic 8-bit Morton counting sort of rays + group bboxes
// ---------------------------------------------------------------------------
__global__ void __launch_bounds__(1024)
prep_kernel(const float* __restrict__ org,
            const float* __restrict__ dir,
            const float* __restrict__ emb,
            const float* __restrict__ chol,
            const float* __restrict__ labels,
            const int*   __restrict__ idx)
{
    const int tid = threadIdx.x;

    if (blockIdx.x < 4) {
        // ---------------- gaussian setup ----------------
        int k = blockIdx.x * 1024 + tid;
        int m = __ldg(idx + k);
        const float4* c4 = reinterpret_cast<const float4*>(chol) + (size_t)m * 4;
        float4 r0 = c4[0], r1 = c4[1], r2 = c4[2], r3 = c4[3];
        float L00 = r0.x;
        float L10 = r1.x, L11 = r1.y;
        float L20 = r2.x, L21 = r2.y, L22 = r2.z;
        float L30 = r3.x, L31 = r3.y, L32 = r3.z, L33 = r3.w;

        float i0 = 1.0f / L00, i1 = 1.0f / L11, i2 = 1.0f / L22, i3 = 1.0f / L33;

        float U00 = i0, U11 = i1, U22 = i2, U33 = i3;
        float U10 = -(L10 * U00) * i1;
        float U20 = -(L20 * U00 + L21 * U10) * i2;
        float U21 = -(L21 * U11) * i2;
        float U30 = -(L30 * U00 + L31 * U10 + L32 * U20) * i3;
        float U31 = -(L31 * U11 + L32 * U21) * i3;
        float U32 = -(L32 * U22) * i3;

        const float s = SCALE_S;
        U00 *= s; U10 *= s; U11 *= s; U20 *= s; U21 *= s; U22 *= s;
        U30 *= s; U31 *= s; U32 *= s; U33 *= s;

        float4 mu = reinterpret_cast<const float4*>(emb)[m];
        float nc0 = -(U00 * mu.x);
        float nc1 = -(U10 * mu.x + U11 * mu.y);
        float nc2 = -(U20 * mu.x + U21 * mu.y + U22 * mu.z);
        float nc3 = -(U30 * mu.x + U31 * mu.y + U32 * mu.z + U33 * mu.w);
        float lab = __ldg(labels + m);

        float4* co = reinterpret_cast<float4*>(g_coef + (size_t)k * 16);
        co[0] = make_float4(U00, U10, U11, U20);
        co[1] = make_float4(U21, U22, U30, U31);
        co[2] = make_float4(U32, U33, nc0, nc1);
        co[3] = make_float4(nc2, nc3, lab, 0.0f);

        float4* ao = reinterpret_cast<float4*>(g_abs + (size_t)k * 12);
        ao[0] = make_float4(fabsf(U00), fabsf(U10), fabsf(U11), fabsf(U20));
        ao[1] = make_float4(fabsf(U21), fabsf(U22), fabsf(U30), fabsf(U31));
        ao[2] = make_float4(fabsf(U32), fabsf(U33), 0.0f, 0.0f);
        return;
    }

    // ---------------- ray sort (block 4) ----------------
    __shared__ unsigned warpcnt[32][256];   // per-warp per-key counts -> warp offsets
    __shared__ unsigned totals[256];
    __shared__ unsigned base[256];

    const int lane = tid & 31;
    const int w    = tid >> 5;

    for (int i = tid; i < 32 * 256; i += 1024)
        (&warpcnt[0][0])[i] = 0u;
    __syncthreads();

    // each thread: 8 consecutive rays [8*tid, 8*tid+8)
    float4 rp[8];
    int    key8[8];
    int    rank8[8];
    const float2* o2 = reinterpret_cast<const float2*>(org);
    const float2* d2 = reinterpret_cast<const float2*>(dir);
#pragma unroll
    for (int s = 0; s < 8; s++) {
        int n = 8 * tid + s;
        float2 o = o2[n];
        float2 d = d2[n];
        rp[s] = make_float4(o.x, o.y, d.x, d.y);
        int bx = min(3, max(0, (int)(o.x * 4.0f)));
        int by = min(3, max(0, (int)(o.y * 4.0f)));
        int cx = min(3, max(0, (int)(d.x * 4.0f)));
        int cy = min(3, max(0, (int)(d.y * 4.0f)));
        // Morton-ish interleave: high bits first
        key8[s] = ((bx >> 1) << 7) | ((by >> 1) << 6) | ((cx >> 1) << 5) | ((cy >> 1) << 4)
                | ((bx & 1) << 3) | ((by & 1) << 2) | ((cx & 1) << 1) | (cy & 1);
    }

    // Phase 1: stable per-warp ranks (order = (warp, step, lane))
#pragma unroll
    for (int s = 0; s < 8; s++) {
        int k = key8[s];
        unsigned mask = __match_any_sync(0xFFFFFFFFu, k);
        unsigned lt   = mask & ((1u << lane) - 1u);
        unsigned cur  = warpcnt[w][k];
        rank8[s] = (int)(cur + __popc(lt));
        __syncwarp();
        if (lt == 0u)  // leader of this key
            warpcnt[w][k] = cur + (unsigned)__popc(mask);
        __syncwarp();
    }
    __syncthreads();

    // Phase 2a: column scans -> warp offsets + totals
    if (tid < 256) {
        unsigned off = 0;
#pragma unroll
        for (int ww = 0; ww < 32; ww++) {
            unsigned c = warpcnt[ww][tid];
            warpcnt[ww][tid] = off;
            off += c;
        }
        totals[tid] = off;
    }
    __syncthreads();
    // Phase 2b: exclusive scan of totals -> base (1 warp, 8 keys/lane)
    // FIXED: proper Hillis-Steele inclusive scan, then excl = inc - loc.
    if (tid < 32) {
        unsigned v[8], loc = 0;
#pragma unroll
        for (int i = 0; i < 8; i++) { v[i] = totals[tid * 8 + i]; loc += v[i]; }
        unsigned inc = loc;
#pragma unroll
        for (int ofs = 1; ofs < 32; ofs <<= 1) {
            unsigned t = __shfl_up_sync(0xFFFFFFFFu, inc, ofs);
            if (lane >= ofs) inc += t;
        }
        unsigned run = inc - loc;   // exclusive prefix across lanes
#pragma unroll
        for (int i = 0; i < 8; i++) { base[tid * 8 + i] = run; run += v[i]; }
    }
    __syncthreads();

    // Phase 3: scatter
#pragma unroll
    for (int s = 0; s < 8; s++) {
        int k = key8[s];
        int pos = (int)(base[k] + warpcnt[w][k]) + rank8[s];
        g_rays[pos] = rp[s];
        g_perm[pos] = 8 * tid + s;
    }
    __syncthreads();
    __threadfence_block();

    // Phase 4: group bboxes (64 groups, warp per group, 2 rounds)
    for (int g = w; g < NGROUP; g += 32) {
        float lx = 1e30f, ly = 1e30f, lz = 1e30f, lw = 1e30f;
        float hx = -1e30f, hy = -1e30f, hz = -1e30f, hw = -1e30f;
        for (int i = lane; i < GSZ; i += 32) {
            float4 p = g_rays[g * GSZ + i];
            lx = fminf(lx, p.x); hx = fmaxf(hx, p.x);
            ly = fminf(ly, p.y); hy = fmaxf(hy, p.y);
            lz = fminf(lz, p.z); hz = fmaxf(hz, p.z);
            lw = fminf(lw, p.w); hw = fmaxf(hw, p.w);
        }
#pragma unroll
        for (int ofs = 16; ofs > 0; ofs >>= 1) {
            lx = fminf(lx, __shfl_xor_sync(0xFFFFFFFFu, lx, ofs));
            hx = fmaxf(hx, __shfl_xor_sync(0xFFFFFFFFu, hx, ofs));
            ly = fminf(ly, __shfl_xor_sync(0xFFFFFFFFu, ly, ofs));
            hy = fmaxf(hy, __shfl_xor_sync(0xFFFFFFFFu, hy, ofs));
            lz = fminf(lz, __shfl_xor_sync(0xFFFFFFFFu, lz, ofs));
            hz = fmaxf(hz, __shfl_xor_sync(0xFFFFFFFFu, hz, ofs));
            lw = fminf(lw, __shfl_xor_sync(0xFFFFFFFFu, lw, ofs));
            hw = fmaxf(hw, __shfl_xor_sync(0xFFFFFFFFu, hw, ofs));
        }
        if (lane == 0) {
            g_gctr[g] = make_float4(0.5f * (lx + hx), 0.5f * (ly + hy),
                                    0.5f * (lz + hz), 0.5f * (lw + hw));
            g_ghw[g]  = make_float4(0.5f * (hx - lx) + 1e-6f, 0.5f * (hy - ly) + 1e-6f,
                                    0.5f * (hz - lz) + 1e-6f, 0.5f * (hw - lw) + 1e-6f);
        }
    }
}

// ---------------------------------------------------------------------------
// Kernel B: eval. grid (NGROUP, GRIDY), block 128 (4 warps).
// Warp tests its 128-gaussian slice vs group bbox, compacts survivors to
// shared, then dense FMA eval over the group's 128 rays (4 per thread).
// ---------------------------------------------------------------------------
__global__ void __launch_bounds__(128)
eval_kernel(float* __restrict__ partial)
{
    __shared__ float4 sbuf[EV_WARPS * GSZ * 4];   // 32 KB: per-warp survivor coeffs

    const int tid  = threadIdx.x;
    const int lane = tid & 31;
    const int w    = tid >> 5;
    const int grp  = blockIdx.x;

    float4 c = g_gctr[grp];
    float4 r = g_ghw[grp];

    const int slotbase = grp * GSZ + lane * 4;
    float4 ray0 = g_rays[slotbase + 0];
    float4 ray1 = g_rays[slotbase + 1];
    float4 ray2 = g_rays[slotbase + 2];
    float4 ray3 = g_rays[slotbase + 3];
    float a0acc = 0.0f, a1acc = 0.0f, a2acc = 0.0f, a3acc = 0.0f;

    const int kbase = blockIdx.y * (KG / GRIDY) + w * (KG / NCOL);  // 512/warp-block, 128/warp
    float4* mybuf = sbuf + w * (GSZ * 4);
    int nsurv = 0;

#pragma unroll
    for (int t = 0; t < 4; t++) {
        int k = kbase + t * 32 + lane;
        const float4* cf = reinterpret_cast<const float4*>(g_coef + (size_t)k * 16);
        float4 f0 = cf[0], f1 = cf[1], f2 = cf[2], f3 = cf[3];
        const float4* af = reinterpret_cast<const float4*>(g_abs + (size_t)k * 12);
        float4 b0 = af[0], b1 = af[1], b2 = af[2];

        // interval bound: y_i over bbox
        float yc0 = __fmaf_rn(f0.x, c.x, f2.z);
        float rh0 = b0.x * r.x;
        float yc1 = __fmaf_rn(f0.y, c.x, f2.w); yc1 = __fmaf_rn(f0.z, c.y, yc1);
        float rh1 = __fmaf_rn(b0.z, r.y, b0.y * r.x);
        float yc2 = __fmaf_rn(f0.w, c.x, f3.x); yc2 = __fmaf_rn(f1.x, c.y, yc2);
        yc2 = __fmaf_rn(f1.y, c.z, yc2);
        float rh2 = __fmaf_rn(b1.y, r.z, __fmaf_rn(b1.x, r.y, b0.w * r.x));
        float yc3 = __fmaf_rn(f1.z, c.x, f3.y); yc3 = __fmaf_rn(f1.w, c.y, yc3);
        yc3 = __fmaf_rn(f2.x, c.z, yc3); yc3 = __fmaf_rn(f2.y, c.w, yc3);
        float rh3 = __fmaf_rn(b2.y, r.w, __fmaf_rn(b2.x, r.z,
                    __fmaf_rn(b1.w, r.y, b1.z * r.x)));

        float m0 = fmaxf(fabsf(yc0) - rh0, 0.0f);
        float m1 = fmaxf(fabsf(yc1) - rh1, 0.0f);
        float m2 = fmaxf(fabsf(yc2) - rh2, 0.0f);
        float m3 = fmaxf(fabsf(yc3) - rh3, 0.0f);
        float qmin = __fmaf_rn(m0, m0, __fmaf_rn(m1, m1,
                     __fmaf_rn(m2, m2, m3 * m3)));

        bool sv = qmin < QCUT;
        unsigned mask = __ballot_sync(0xFFFFFFFFu, sv);
        if (sv) {
            int slot = nsurv + __popc(mask & ((1u << lane) - 1u));
            float4* dst = mybuf + slot * 4;
            dst[0] = f0; dst[1] = f1; dst[2] = f2; dst[3] = f3;
        }
        nsurv += __popc(mask);
    }
    __syncwarp();

    for (int i = 0; i < nsurv; i++) {
        const float4* sp = mybuf + i * 4;
        float4 f0 = sp[0], f1 = sp[1], f2 = sp[2], f3 = sp[3];

#define EVAL_RAY(RAY, ACC)                                                  \
        {                                                                   \
            float y0 = __fmaf_rn(f0.x, RAY.x, f2.z);                        \
            float y1 = __fmaf_rn(f0.y, RAY.x, f2.w);                        \
            y1 = __fmaf_rn(f0.z, RAY.y, y1);                                \
            float y2 = __fmaf_rn(f0.w, RAY.x, f3.x);                        \
            y2 = __fmaf_rn(f1.x, RAY.y, y2);                                \
            y2 = __fmaf_rn(f1.y, RAY.z, y2);                                \
            float y3 = __fmaf_rn(f1.z, RAY.x, f3.y);                        \
            y3 = __fmaf_rn(f1.w, RAY.y, y3);                                \
            y3 = __fmaf_rn(f2.x, RAY.z, y3);                                \
            y3 = __fmaf_rn(f2.y, RAY.w, y3);                                \
            float qn = -(y0 * y0);                                          \
            qn = __fmaf_rn(y1, -y1, qn);                                    \
            qn = __fmaf_rn(y2, -y2, qn);                                    \
            qn = __fmaf_rn(y3, -y3, qn);                                    \
            ACC = __fmaf_rn(f3.z, ex2f(qn), ACC);                           \
        }
        EVAL_RAY(ray0, a0acc)
        EVAL_RAY(ray1, a1acc)
        EVAL_RAY(ray2, a2acc)
        EVAL_RAY(ray3, a3acc)
#undef EVAL_RAY
    }

    const int col = blockIdx.y * EV_WARPS + w;
    partial[(size_t)(slotbase + 0) * NCOL + col] = a0acc;
    partial[(size_t)(slotbase + 1) * NCOL + col] = a1acc;
    partial[(size_t)(slotbase + 2) * NCOL + col] = a2acc;
    partial[(size_t)(slotbase + 3) * NCOL + col] = a3acc;
}

// ---------------------------------------------------------------------------
// Kernel C: reduce NCOL partials per sorted slot, sigmoid, scatter via perm.
// ---------------------------------------------------------------------------
__global__ void __launch_bounds__(128)
reduce_kernel(const float* __restrict__ partial, float* __restrict__ out)
{
    int slot = blockIdx.x * 128 + threadIdx.x;
    const float4* p = reinterpret_cast<const float4*>(partial + (size_t)slot * NCOL);
    float s = 0.0f;
#pragma unroll
    for (int i = 0; i < NCOL / 4; i++) {
        float4 v = p[i];
        s += (v.x + v.y) + (v.z + v.w);
    }
    float e = ex2f(-s * 1.4426950408889634f);
    out[g_perm[slot]] = 1.0f / (1.0f + e);
}

// ---------------------------------------------------------------------------
extern "C" void kernel_launch(void* const* d_in, const int* in_sizes, int n_in,
                              void* d_out, int out_size)
{
    const float* origins    = (const float*)d_in[0];
    const float* directions = (const float*)d_in[1];
    const float* embeddings = (const float*)d_in[2];
    const float* chol       = (const float*)d_in[3];
    const float* labels     = (const float*)d_in[4];
    const int*   idx        = (const int*)  d_in[5];
    float* out = (float*)d_out;

    float* part_ptr = nullptr;
    cudaGetSymbolAddress((void**)&part_ptr, g_partial);

    prep_kernel<<<5, 1024>>>(origins, directions, embeddings, chol, labels, idx);
    eval_kernel<<<dim3(NGROUP, GRIDY), 128>>>(part_ptr);
    reduce_kernel<<<NRAYS / 128, 128>>>(part_ptr, out);
}

// round 5
// speedup vs baseline: 1.0613x; 1.0613x over previous
#include <cuda_runtime.h>
#include <cuda_bf16.h>

// Problem constants
#define NRAYS   8192
#define KG      4096
#define NGROUP  64          // ray groups (equal size)
#define GSZ     128         // rays per group
#define GRIDY   8           // gaussian splits per group (blockIdx.y)
#define EV_WARPS 4          // warps per eval block
#define NCOL    (GRIDY * EV_WARPS)   // 32 partial columns
#define QCUT    24.0f       // skip if q_min > QCUT (worst-case rel err <= 4096*2^-24 = 2.4e-4)

// s = sqrt(0.5 * log2(e)) : folds exp(-0.5 q) -> 2^(-||W d||^2)
#define SCALE_S 0.8493281132464818f

#define SETUP_BLOCKS 32     // gaussian-setup blocks (128 gaussians each)

// ---- scratch (__device__ globals; no allocations) -------------------------
__device__ __align__(16) float  g_coef[KG * 16];            // W(10), nc(4), lab, pad
__device__ __align__(16) float  g_abs [KG * 12];            // |W|(10), pad(2)
__device__ __align__(16) float4 g_rays[NRAYS];              // sorted rays
__device__ int    g_perm[NRAYS];                            // sorted slot -> original n
__device__ float  g_partial[NRAYS * NCOL];                  // 1 MB

__device__ __forceinline__ float ex2f(float x) {
    float e;
    asm("ex2.approx.ftz.f32 %0, %1;" : "=f"(e) : "f"(x));
    return e;
}

// ---------------------------------------------------------------------------
// Kernel A: grid SETUP_BLOCKS+1.
//   blocks 0..31 : gaussian setup, 128 gaussians each (threads 0..127 active)
//   block  32    : deterministic 8-bit Morton counting sort of rays (1024 thr)
// ---------------------------------------------------------------------------
__global__ void __launch_bounds__(1024)
prep_kernel(const float* __restrict__ org,
            const float* __restrict__ dir,
            const float* __restrict__ emb,
            const float* __restrict__ chol,
            const float* __restrict__ labels,
            const int*   __restrict__ idx)
{
    const int tid = threadIdx.x;

    if (blockIdx.x < SETUP_BLOCKS) {
        // ---------------- gaussian setup (spread over 32 SMs) ----------------
        if (tid >= 128) return;
        int k = blockIdx.x * 128 + tid;
        int m = __ldg(idx + k);
        const float4* c4 = reinterpret_cast<const float4*>(chol) + (size_t)m * 4;
        float4 r0 = c4[0], r1 = c4[1], r2 = c4[2], r3 = c4[3];
        float L00 = r0.x;
        float L10 = r1.x, L11 = r1.y;
        float L20 = r2.x, L21 = r2.y, L22 = r2.z;
        float L30 = r3.x, L31 = r3.y, L32 = r3.z, L33 = r3.w;

        float i0 = 1.0f / L00, i1 = 1.0f / L11, i2 = 1.0f / L22, i3 = 1.0f / L33;

        float U00 = i0, U11 = i1, U22 = i2, U33 = i3;
        float U10 = -(L10 * U00) * i1;
        float U20 = -(L20 * U00 + L21 * U10) * i2;
        float U21 = -(L21 * U11) * i2;
        float U30 = -(L30 * U00 + L31 * U10 + L32 * U20) * i3;
        float U31 = -(L31 * U11 + L32 * U21) * i3;
        float U32 = -(L32 * U22) * i3;

        const float s = SCALE_S;
        U00 *= s; U10 *= s; U11 *= s; U20 *= s; U21 *= s; U22 *= s;
        U30 *= s; U31 *= s; U32 *= s; U33 *= s;

        float4 mu = reinterpret_cast<const float4*>(emb)[m];
        float nc0 = -(U00 * mu.x);
        float nc1 = -(U10 * mu.x + U11 * mu.y);
        float nc2 = -(U20 * mu.x + U21 * mu.y + U22 * mu.z);
        float nc3 = -(U30 * mu.x + U31 * mu.y + U32 * mu.z + U33 * mu.w);
        float lab = __ldg(labels + m);

        float4* co = reinterpret_cast<float4*>(g_coef + (size_t)k * 16);
        co[0] = make_float4(U00, U10, U11, U20);
        co[1] = make_float4(U21, U22, U30, U31);
        co[2] = make_float4(U32, U33, nc0, nc1);
        co[3] = make_float4(nc2, nc3, lab, 0.0f);

        float4* ao = reinterpret_cast<float4*>(g_abs + (size_t)k * 12);
        ao[0] = make_float4(fabsf(U00), fabsf(U10), fabsf(U11), fabsf(U20));
        ao[1] = make_float4(fabsf(U21), fabsf(U22), fabsf(U30), fabsf(U31));
        ao[2] = make_float4(fabsf(U32), fabsf(U33), 0.0f, 0.0f);
        return;
    }

    // ---------------- ray sort (block SETUP_BLOCKS) ----------------
    __shared__ unsigned warpcnt[32][256];   // per-warp per-key counts -> warp offsets
    __shared__ unsigned totals[256];
    __shared__ unsigned base[256];

    const int lane = tid & 31;
    const int w    = tid >> 5;

    for (int i = tid; i < 32 * 256; i += 1024)
        (&warpcnt[0][0])[i] = 0u;
    __syncthreads();

    const float2* o2 = reinterpret_cast<const float2*>(org);
    const float2* d2 = reinterpret_cast<const float2*>(dir);

    // each thread: 8 consecutive rays; keep only keys/ranks in regs
    int key8[8];
    int rank8[8];
#pragma unroll
    for (int s = 0; s < 8; s++) {
        int n = 8 * tid + s;
        float2 o = o2[n];
        float2 d = d2[n];
        int bx = min(3, max(0, (int)(o.x * 4.0f)));
        int by = min(3, max(0, (int)(o.y * 4.0f)));
        int cx = min(3, max(0, (int)(d.x * 4.0f)));
        int cy = min(3, max(0, (int)(d.y * 4.0f)));
        key8[s] = ((bx >> 1) << 7) | ((by >> 1) << 6) | ((cx >> 1) << 5) | ((cy >> 1) << 4)
                | ((bx & 1) << 3) | ((by & 1) << 2) | ((cx & 1) << 1) | (cy & 1);
    }

    // Phase 1: stable per-warp ranks (order = (warp, step, lane))
#pragma unroll
    for (int s = 0; s < 8; s++) {
        int k = key8[s];
        unsigned mask = __match_any_sync(0xFFFFFFFFu, k);
        unsigned lt   = mask & ((1u << lane) - 1u);
        unsigned cur  = warpcnt[w][k];
        rank8[s] = (int)(cur + __popc(lt));
        __syncwarp();
        if (lt == 0u)  // leader of this key
            warpcnt[w][k] = cur + (unsigned)__popc(mask);
        __syncwarp();
    }
    __syncthreads();

    // Phase 2a: column scans -> warp offsets + totals
    if (tid < 256) {
        unsigned off = 0;
#pragma unroll
        for (int ww = 0; ww < 32; ww++) {
            unsigned c = warpcnt[ww][tid];
            warpcnt[ww][tid] = off;
            off += c;
        }
        totals[tid] = off;
    }
    __syncthreads();
    // Phase 2b: exclusive scan of totals (Hillis-Steele inclusive, then -loc)
    if (tid < 32) {
        unsigned v[8], loc = 0;
#pragma unroll
        for (int i = 0; i < 8; i++) { v[i] = totals[tid * 8 + i]; loc += v[i]; }
        unsigned inc = loc;
#pragma unroll
        for (int ofs = 1; ofs < 32; ofs <<= 1) {
            unsigned t = __shfl_up_sync(0xFFFFFFFFu, inc, ofs);
            if (lane >= ofs) inc += t;
        }
        unsigned run = inc - loc;
#pragma unroll
        for (int i = 0; i < 8; i++) { base[tid * 8 + i] = run; run += v[i]; }
    }
    __syncthreads();

    // Phase 3: scatter (reload rays - coalesced, cheap)
#pragma unroll
    for (int s = 0; s < 8; s++) {
        int n = 8 * tid + s;
        float2 o = o2[n];
        float2 d = d2[n];
        int k = key8[s];
        int pos = (int)(base[k] + warpcnt[w][k]) + rank8[s];
        g_rays[pos] = make_float4(o.x, o.y, d.x, d.y);
        g_perm[pos] = n;
    }
}

// ---------------------------------------------------------------------------
// Kernel B: eval. grid (NGROUP, GRIDY), block 128 (4 warps).
// Each warp: computes group bbox from its own ray registers, tests its
// 128-gaussian slice, compacts survivors to shared, dense FMA eval.
// ---------------------------------------------------------------------------
__global__ void __launch_bounds__(128)
eval_kernel(float* __restrict__ partial)
{
    __shared__ float4 sbuf[EV_WARPS * GSZ * 4];   // 32 KB: per-warp survivor coeffs

    const int tid  = threadIdx.x;
    const int lane = tid & 31;
    const int w    = tid >> 5;
    const int grp  = blockIdx.x;

    const int slotbase = grp * GSZ + lane * 4;
    float4 ray0 = g_rays[slotbase + 0];
    float4 ray1 = g_rays[slotbase + 1];
    float4 ray2 = g_rays[slotbase + 2];
    float4 ray3 = g_rays[slotbase + 3];
    float a0acc = 0.0f, a1acc = 0.0f, a2acc = 0.0f, a3acc = 0.0f;

    // ---- per-warp group bbox over the 128 rays held in registers ----
    float lx = fminf(fminf(ray0.x, ray1.x), fminf(ray2.x, ray3.x));
    float hx = fmaxf(fmaxf(ray0.x, ray1.x), fmaxf(ray2.x, ray3.x));
    float ly = fminf(fminf(ray0.y, ray1.y), fminf(ray2.y, ray3.y));
    float hy = fmaxf(fmaxf(ray0.y, ray1.y), fmaxf(ray2.y, ray3.y));
    float lz = fminf(fminf(ray0.z, ray1.z), fminf(ray2.z, ray3.z));
    float hz = fmaxf(fmaxf(ray0.z, ray1.z), fmaxf(ray2.z, ray3.z));
    float lw = fminf(fminf(ray0.w, ray1.w), fminf(ray2.w, ray3.w));
    float hw = fmaxf(fmaxf(ray0.w, ray1.w), fmaxf(ray2.w, ray3.w));
#pragma unroll
    for (int ofs = 16; ofs > 0; ofs >>= 1) {
        lx = fminf(lx, __shfl_xor_sync(0xFFFFFFFFu, lx, ofs));
        hx = fmaxf(hx, __shfl_xor_sync(0xFFFFFFFFu, hx, ofs));
        ly = fminf(ly, __shfl_xor_sync(0xFFFFFFFFu, ly, ofs));
        hy = fmaxf(hy, __shfl_xor_sync(0xFFFFFFFFu, hy, ofs));
        lz = fminf(lz, __shfl_xor_sync(0xFFFFFFFFu, lz, ofs));
        hz = fmaxf(hz, __shfl_xor_sync(0xFFFFFFFFu, hz, ofs));
        lw = fminf(lw, __shfl_xor_sync(0xFFFFFFFFu, lw, ofs));
        hw = fmaxf(hw, __shfl_xor_sync(0xFFFFFFFFu, hw, ofs));
    }
    float4 c = make_float4(0.5f * (lx + hx), 0.5f * (ly + hy),
                           0.5f * (lz + hz), 0.5f * (lw + hw));
    float4 r = make_float4(0.5f * (hx - lx) + 1e-6f, 0.5f * (hy - ly) + 1e-6f,
                           0.5f * (hz - lz) + 1e-6f, 0.5f * (hw - lw) + 1e-6f);

    const int kbase = blockIdx.y * (KG / GRIDY) + w * (KG / NCOL);  // 128/warp
    float4* mybuf = sbuf + w * (GSZ * 4);
    int nsurv = 0;

#pragma unroll
    for (int t = 0; t < 4; t++) {
        int k = kbase + t * 32 + lane;
        const float4* cf = reinterpret_cast<const float4*>(g_coef + (size_t)k * 16);
        float4 f0 = cf[0], f1 = cf[1], f2 = cf[2], f3 = cf[3];
        const float4* af = reinterpret_cast<const float4*>(g_abs + (size_t)k * 12);
        float4 b0 = af[0], b1 = af[1], b2 = af[2];

        // interval bound: y_i over bbox
        float yc0 = __fmaf_rn(f0.x, c.x, f2.z);
        float rh0 = b0.x * r.x;
        float yc1 = __fmaf_rn(f0.y, c.x, f2.w); yc1 = __fmaf_rn(f0.z, c.y, yc1);
        float rh1 = __fmaf_rn(b0.z, r.y, b0.y * r.x);
        float yc2 = __fmaf_rn(f0.w, c.x, f3.x); yc2 = __fmaf_rn(f1.x, c.y, yc2);
        yc2 = __fmaf_rn(f1.y, c.z, yc2);
        float rh2 = __fmaf_rn(b1.y, r.z, __fmaf_rn(b1.x, r.y, b0.w * r.x));
        float yc3 = __fmaf_rn(f1.z, c.x, f3.y); yc3 = __fmaf_rn(f1.w, c.y, yc3);
        yc3 = __fmaf_rn(f2.x, c.z, yc3); yc3 = __fmaf_rn(f2.y, c.w, yc3);
        float rh3 = __fmaf_rn(b2.y, r.w, __fmaf_rn(b2.x, r.z,
                    __fmaf_rn(b1.w, r.y, b1.z * r.x)));

        float m0 = fmaxf(fabsf(yc0) - rh0, 0.0f);
        float m1 = fmaxf(fabsf(yc1) - rh1, 0.0f);
        float m2 = fmaxf(fabsf(yc2) - rh2, 0.0f);
        float m3 = fmaxf(fabsf(yc3) - rh3, 0.0f);
        float qmin = __fmaf_rn(m0, m0, __fmaf_rn(m1, m1,
                     __fmaf_rn(m2, m2, m3 * m3)));

        bool sv = qmin < QCUT;
        unsigned mask = __ballot_sync(0xFFFFFFFFu, sv);
        if (sv) {
            int slot = nsurv + __popc(mask & ((1u << lane) - 1u));
            float4* dst = mybuf + slot * 4;
            dst[0] = f0; dst[1] = f1; dst[2] = f2; dst[3] = f3;
        }
        nsurv += __popc(mask);
    }
    __syncwarp();

    for (int i = 0; i < nsurv; i++) {
        const float4* sp = mybuf + i * 4;
        float4 f0 = sp[0], f1 = sp[1], f2 = sp[2], f3 = sp[3];

#define EVAL_RAY(RAY, ACC)                                                  \
        {                                                                   \
            float y0 = __fmaf_rn(f0.x, RAY.x, f2.z);                        \
            float y1 = __fmaf_rn(f0.y, RAY.x, f2.w);                        \
            y1 = __fmaf_rn(f0.z, RAY.y, y1);                                \
            float y2 = __fmaf_rn(f0.w, RAY.x, f3.x);                        \
            y2 = __fmaf_rn(f1.x, RAY.y, y2);                                \
            y2 = __fmaf_rn(f1.y, RAY.z, y2);                                \
            float y3 = __fmaf_rn(f1.z, RAY.x, f3.y);                        \
            y3 = __fmaf_rn(f1.w, RAY.y, y3);                                \
            y3 = __fmaf_rn(f2.x, RAY.z, y3);                                \
            y3 = __fmaf_rn(f2.y, RAY.w, y3);                                \
            float qn = -(y0 * y0);                                          \
            qn = __fmaf_rn(y1, -y1, qn);                                    \
            qn = __fmaf_rn(y2, -y2, qn);                                    \
            qn = __fmaf_rn(y3, -y3, qn);                                    \
            ACC = __fmaf_rn(f3.z, ex2f(qn), ACC);                           \
        }
        EVAL_RAY(ray0, a0acc)
        EVAL_RAY(ray1, a1acc)
        EVAL_RAY(ray2, a2acc)
        EVAL_RAY(ray3, a3acc)
#undef EVAL_RAY
    }

    const int col = blockIdx.y * EV_WARPS + w;
    partial[(size_t)(slotbase + 0) * NCOL + col] = a0acc;
    partial[(size_t)(slotbase + 1) * NCOL + col] = a1acc;
    partial[(size_t)(slotbase + 2) * NCOL + col] = a2acc;
    partial[(size_t)(slotbase + 3) * NCOL + col] = a3acc;
}

// ---------------------------------------------------------------------------
// Kernel C: reduce NCOL partials per sorted slot, sigmoid, scatter via perm.
// ---------------------------------------------------------------------------
__global__ void __launch_bounds__(128)
reduce_kernel(const float* __restrict__ partial, float* __restrict__ out)
{
    int slot = blockIdx.x * 128 + threadIdx.x;
    const float4* p = reinterpret_cast<const float4*>(partial + (size_t)slot * NCOL);
    float s = 0.0f;
#pragma unroll
    for (int i = 0; i < NCOL / 4; i++) {
        float4 v = p[i];
        s += (v.x + v.y) + (v.z + v.w);
    }
    float e = ex2f(-s * 1.4426950408889634f);
    out[g_perm[slot]] = 1.0f / (1.0f + e);
}

// ---------------------------------------------------------------------------
extern "C" void kernel_launch(void* const* d_in, const int* in_sizes, int n_in,
                              void* d_out, int out_size)
{
    const float* origins    = (const float*)d_in[0];
    const float* directions = (const float*)d_in[1];
    const float* embeddings = (const float*)d_in[2];
    const float* chol       = (const float*)d_in[3];
    const float* labels     = (const float*)d_in[4];
    const int*   idx        = (const int*)  d_in[5];
    float* out = (float*)d_out;

    float* part_ptr = nullptr;
    cudaGetSymbolAddress((void**)&part_ptr, g_partial);

    prep_kernel<<<SETUP_BLOCKS + 1, 1024>>>(origins, directions, embeddings,
                                            chol, labels, idx);
    eval_kernel<<<dim3(NGROUP, GRIDY), 128>>>(part_ptr);
    reduce_kernel<<<NRAYS / 128, 128>>>(part_ptr, out);
}